// round 7
// baseline (speedup 1.0000x reference)
#include <cuda_runtime.h>
#include <cstdint>
#include <math.h>

#define BB_L 200
#define BB_D 128
#define BB_H 100
#define NT 1024

// ---- SMEM layout (float indices) ----
// xa: tf32 pairs uint2[224 rows][68]  -> 30464 f (121856 B)
// B : packed uint4[4096] (64KB)      -> 16384 f
#define OFF_XA  0
#define OFF_WK  30464
#define OFF_CV  (OFF_WK + 16384)    // (cj, vv) float2[128] -> 256 f
#define OFF_QS  (OFF_CV + 256)      // 128 f
#define OFF_SC  (OFF_QS + 128)      // 208 f
#define OFF_MK  (OFF_SC + 208)      // 208 f
#define OFF_SCP (OFF_MK + 208)      // partial scores [208][4] -> 832 f
#define OFF_RED (OFF_SCP + 832)     // 16 f
#define SMEM_FLOATS (OFF_RED + 16)
#define SMEM_BYTES (SMEM_FLOATS * 4)

// packed B in fragment order: u4idx = ((ks*8+g)*4+t)*8 + (ntp ^ ((4g+t)&7))
__device__ uint4 g_wkp[4096];

__device__ __forceinline__ uint32_t to_tf32(float f) {
    uint32_t r;
    asm("cvt.rna.tf32.f32 %0, %1;" : "=r"(r) : "f"(f));
    return r;
}
__device__ __forceinline__ float tanh_fast(float x) {
    float y;
    asm("tanh.approx.f32 %0, %1;" : "=f"(y) : "f"(x));
    return y;
}
__device__ __forceinline__ void mma_tf32(float* c,
                                         uint32_t a0, uint32_t a1, uint32_t a2, uint32_t a3,
                                         uint32_t b0, uint32_t b1) {
    asm volatile(
        "mma.sync.aligned.m16n8k8.row.col.f32.tf32.tf32.f32 "
        "{%0,%1,%2,%3}, {%4,%5,%6,%7}, {%8,%9}, {%0,%1,%2,%3};"
        : "+f"(c[0]), "+f"(c[1]), "+f"(c[2]), "+f"(c[3])
        : "r"(a0), "r"(a1), "r"(a2), "r"(a3), "r"(b0), "r"(b1));
}

// ---------------- prep: pack Wk fragments (tf32), swizzled ----------------
__global__ void pack_wk_kernel(const float* __restrict__ Wk) {
    int i = blockIdx.x * 256 + threadIdx.x;   // u4 index, 0..4095
    if (i >= 4096) return;
    int phys = i & 7;
    int row = i >> 3;            // (ks*8+g)*4+t
    int t = row & 3;
    int g = (row >> 2) & 7;
    int ks = row >> 5;
    int h = (4 * g + t) & 7;
    int ntp = phys ^ h;          // logical nt pair
    int nt0 = 2 * ntp, nt1 = 2 * ntp + 1;
    int j0 = 8 * nt0 + g, j1 = 8 * nt1 + g;
    int d0 = 8 * ks + t, d1 = d0 + 4;
    uint4 o;
    o.x = (j0 < BB_H) ? to_tf32(Wk[d0 * BB_H + j0]) : 0u;
    o.y = (j0 < BB_H) ? to_tf32(Wk[d1 * BB_H + j0]) : 0u;
    o.z = (j1 < BB_H) ? to_tf32(Wk[d0 * BB_H + j1]) : 0u;
    o.w = (j1 < BB_H) ? to_tf32(Wk[d1 * BB_H + j1]) : 0u;
    g_wkp[i] = o;
}

__global__ void __launch_bounds__(NT, 1)
mxqa_mma_kernel(const float* __restrict__ x, const float* __restrict__ q,
                const float* __restrict__ bk,
                const float* __restrict__ Wq, const float* __restrict__ v,
                float* __restrict__ out)
{
    extern __shared__ float sm[];
    uint2* xa2 = reinterpret_cast<uint2*>(sm + OFF_XA);
    uint4* xa4 = reinterpret_cast<uint4*>(sm + OFF_XA);
    const uint4* bw = reinterpret_cast<const uint4*>(sm + OFF_WK);
    float2* cvv = reinterpret_cast<float2*>(sm + OFF_CV);
    float* qs = sm + OFF_QS;
    float* sc = sm + OFF_SC;
    float* mk = sm + OFF_MK;
    float* scp = sm + OFF_SCP;
    float* red = sm + OFF_RED;

    const int tid = threadIdx.x;
    const int lane = tid & 31;
    const int warp = tid >> 5;
    const int b = blockIdx.x;
    const int g = lane >> 2;
    const int t = lane & 3;

    // ---------------- Phase 1: staging ----------------
    if (tid < 128) qs[tid] = q[(long long)b * 128 + tid];
    if (tid < 208) { sc[tid] = 0.f; mk[tid] = 0.f; }

    // zero xa rows 200..223 (24 * 136 floats)
    for (int i = tid; i < 24 * 136; i += NT)
        sm[OFF_XA + 200 * 136 + i] = 0.f;

    // packed B: straight copy of 4096 uint4
    {
        const uint4* src = g_wkp;
        uint4* dst = reinterpret_cast<uint4*>(sm + OFF_WK);
        for (int i = tid; i < 4096; i += NT) dst[i] = src[i];
    }

    // x -> tf32 pairs; mask from original fp32
    {
        const float4* xb4 = reinterpret_cast<const float4*>(x + (long long)b * (BB_L * BB_D));
        for (int u = tid; u < BB_L * 16; u += NT) {
            int l = u >> 4;
            int ks = u & 15;
            float4 f0 = xb4[2 * u];
            float4 f1 = xb4[2 * u + 1];
            uint4 o0, o1;   // pairs (x[8k+t], x[8k+t+4]) for t=0,1 and 2,3
            o0.x = to_tf32(f0.x); o0.y = to_tf32(f1.x);
            o0.z = to_tf32(f0.y); o0.w = to_tf32(f1.y);
            o1.x = to_tf32(f0.z); o1.y = to_tf32(f1.z);
            o1.z = to_tf32(f0.w); o1.w = to_tf32(f1.w);
            xa4[l * 34 + 2 * ks] = o0;
            xa4[l * 34 + 2 * ks + 1] = o1;
            if (f0.x != 0.f || f0.y != 0.f || f0.z != 0.f || f0.w != 0.f ||
                f1.x != 0.f || f1.y != 0.f || f1.z != 0.f || f1.w != 0.f)
                mk[l] = 1.f;   // benign race
        }
    }
    __syncthreads();

    // ---------------- Phase 2: GEMM (warps 0-27) || cj (warps 28-31) ----------------
    float acc[2][4][4];
    const int mb = warp >> 2;   // 0..6
    const int nb = warp & 3;    // 0..3
    if (warp < 28) {
        const uint2* pa = xa2 + (32 * mb + g) * 68 + t;
        const int h = (4 * g + t) & 7;
        const uint4* pbr = bw + (g * 4 + t) * 8;
        const uint4* pb0 = pbr + ((2 * nb) ^ h);
        const uint4* pb1 = pbr + ((2 * nb + 1) ^ h);
#pragma unroll
        for (int m = 0; m < 2; ++m)
#pragma unroll
            for (int n = 0; n < 4; ++n)
#pragma unroll
                for (int k = 0; k < 4; ++k) acc[m][n][k] = 0.f;

#pragma unroll
        for (int ks = 0; ks < 16; ++ks) {
            uint2 p00 = pa[4 * ks];
            uint2 p01 = pa[4 * ks + 8 * 68];
            uint2 p10 = pa[4 * ks + 16 * 68];
            uint2 p11 = pa[4 * ks + 24 * 68];
            uint4 B0 = pb0[ks * 256];
            uint4 B1 = pb1[ks * 256];
            mma_tf32(acc[0][0], p00.x, p01.x, p00.y, p01.y, B0.x, B0.y);
            mma_tf32(acc[0][1], p00.x, p01.x, p00.y, p01.y, B0.z, B0.w);
            mma_tf32(acc[0][2], p00.x, p01.x, p00.y, p01.y, B1.x, B1.y);
            mma_tf32(acc[0][3], p00.x, p01.x, p00.y, p01.y, B1.z, B1.w);
            mma_tf32(acc[1][0], p10.x, p11.x, p10.y, p11.y, B0.x, B0.y);
            mma_tf32(acc[1][1], p10.x, p11.x, p10.y, p11.y, B0.z, B0.w);
            mma_tf32(acc[1][2], p10.x, p11.x, p10.y, p11.y, B1.x, B1.y);
            mma_tf32(acc[1][3], p10.x, p11.x, p10.y, p11.y, B1.z, B1.w);
        }
    } else {
        // cj[j] = bk[j] + sum_d q[d]*Wq[d][j]; vv[j] = v[j]; padded to 128
        const int j = tid - 28 * 32;   // 0..127
        float s = 0.f, vw = 0.f;
        if (j < BB_H) {
            s = bk[j];
#pragma unroll 8
            for (int d = 0; d < 128; ++d) s += qs[d] * Wq[d * BB_H + j];
            vw = v[j];
        }
        cvv[j] = make_float2(s, vw);
    }
    __syncthreads();

    // ---------------- Phase 3: epilogue on fragments ----------------
    if (warp < 28) {
#pragma unroll
        for (int m = 0; m < 2; ++m) {
            float s0 = 0.f, s1 = 0.f;
#pragma unroll
            for (int n = 0; n < 4; ++n) {
                int j0 = 32 * nb + 8 * n + 2 * t;
                float2 c0 = cvv[j0];
                float2 c1 = cvv[j0 + 1];
                s0 += tanh_fast(acc[m][n][0] + c0.x) * c0.y;
                s0 += tanh_fast(acc[m][n][1] + c1.x) * c1.y;
                s1 += tanh_fast(acc[m][n][2] + c0.x) * c0.y;
                s1 += tanh_fast(acc[m][n][3] + c1.x) * c1.y;
            }
            s0 += __shfl_xor_sync(0xffffffffu, s0, 1);
            s0 += __shfl_xor_sync(0xffffffffu, s0, 2);
            s1 += __shfl_xor_sync(0xffffffffu, s1, 1);
            s1 += __shfl_xor_sync(0xffffffffu, s1, 2);
            if (t == 0) {
                int l0 = 32 * mb + 16 * m + g;
                int l1 = l0 + 8;
                if (l0 < 208) scp[4 * l0 + nb] = s0;
                if (l1 < 208) scp[4 * l1 + nb] = s1;
            }
        }
    }
    __syncthreads();

    // ---------------- Phase 4: combine, exp, normalize ----------------
    {
        float a = 0.f;
        if (tid < 208) {
            a = expf(scp[4 * tid] + scp[4 * tid + 1] + scp[4 * tid + 2] + scp[4 * tid + 3]) * mk[tid];
            sc[tid] = a;
        }
        if (warp < 7) {
#pragma unroll
            for (int o = 16; o; o >>= 1) a += __shfl_xor_sync(0xffffffffu, a, o);
            if (lane == 0) red[warp] = a;
        }
    }
    __syncthreads();
    if (tid == 0) {
        float tsum = 0.f;
#pragma unroll
        for (int w = 0; w < 7; ++w) tsum += red[w];
        red[0] = 1.f / (tsum + 1e-7f);
    }
    __syncthreads();
    const float winv = red[0];

    // ---------------- Phase 5: out[b][d] from GLOBAL x (full fp32) ----------------
    {
        const int d = tid & 127;
        const int oct = tid >> 7;            // 0..7
        const float* xg = x + (long long)b * (BB_L * BB_D) + (oct * 25) * 128 + d;
        float a = 0.f;
#pragma unroll 5
        for (int i = 0; i < 25; ++i)
            a += sc[oct * 25 + i] * xg[i * 128];
        sm[OFF_WK + tid] = a;                // reuse B region
    }
    __syncthreads();
    if (tid < 128) {
        float o = 0.f;
#pragma unroll
        for (int k = 0; k < 8; ++k) o += sm[OFF_WK + tid + 128 * k];
        out[(long long)b * 128 + tid] = o * winv;
    }
}

extern "C" void kernel_launch(void* const* d_in, const int* in_sizes, int n_in,
                              void* d_out, int out_size)
{
    const float* x  = (const float*)d_in[0];
    const float* q  = (const float*)d_in[1];
    const float* Wk = (const float*)d_in[2];
    const float* bk = (const float*)d_in[3];
    const float* Wq = (const float*)d_in[4];
    const float* v  = (const float*)d_in[5];
    float* out = (float*)d_out;

    const int B = in_sizes[1] / BB_D;  // q is [B, 128]

    pack_wk_kernel<<<16, 256>>>(Wk);

    cudaFuncSetAttribute(mxqa_mma_kernel, cudaFuncAttributeMaxDynamicSharedMemorySize, SMEM_BYTES);
    mxqa_mma_kernel<<<B, NT, SMEM_BYTES>>>(x, q, bk, Wq, v, out);
}